// round 6
// baseline (speedup 1.0000x reference)
#include <cuda_runtime.h>
#include <cuda_bf16.h>
#include <cstdint>

// Problem constants
#define BB 8
#define TT 128
#define SS 512
#define DD 128
#define CLUSTER 8
#define SSLICE (SS / CLUSTER)   // 64 encoder rows per rank
#define NTHR 512
#define NWARP 16

// Scratch (allocation-free rule: __device__ globals)
__device__ float g_HU[BB * SS * DD];   // H @ Ua, [B,S,D]
__device__ float g_XG[BB * TT * 512];  // x@W + bias for 4 gates (i,f,c,o), [B,T,512]

__device__ __forceinline__ float tanh_ap(float x) {
    float y;
    asm("tanh.approx.f32 %0, %1;" : "=f"(y) : "f"(x));
    return y;
}
__device__ __forceinline__ float4 ldg4(const float* p) {
    return __ldg(reinterpret_cast<const float4*>(p));
}
__device__ __forceinline__ uint32_t smem_u32(const void* p) {
    uint32_t a;
    asm("{ .reg .u64 t; cvta.to.shared.u64 t, %1; cvt.u32.u64 %0, t; }" : "=r"(a) : "l"(p));
    return a;
}
// st.async a float to the SAME smem offset on cluster CTA `rank`, completing
// tx bytes on that rank's mbarrier.
__device__ __forceinline__ void st_async_remote(uint32_t laddr, uint32_t lmbar,
                                                uint32_t rank, float v) {
    uint32_t ra, rb;
    asm volatile("mapa.shared::cluster.u32 %0, %1, %2;" : "=r"(ra) : "r"(laddr), "r"(rank));
    asm volatile("mapa.shared::cluster.u32 %0, %1, %2;" : "=r"(rb) : "r"(lmbar), "r"(rank));
    asm volatile("st.async.shared::cluster.mbarrier::complete_tx::bytes.b32 [%0], %1, [%2];"
                 :: "r"(ra), "r"(__float_as_uint(v)), "r"(rb) : "memory");
}
__device__ __forceinline__ void mbar_init(uint32_t addr, uint32_t count) {
    asm volatile("mbarrier.init.shared.b64 [%0], %1;" :: "r"(addr), "r"(count) : "memory");
}
__device__ __forceinline__ void mbar_expect_tx(uint32_t addr, uint32_t bytes) {
    asm volatile("mbarrier.arrive.expect_tx.shared.b64 _, [%0], %1;"
                 :: "r"(addr), "r"(bytes) : "memory");
}
__device__ __forceinline__ void mbar_wait(uint32_t addr, uint32_t parity) {
    uint32_t done;
    asm volatile(
        "{\n\t.reg .pred p;\n\t"
        "mbarrier.try_wait.parity.acquire.cta.shared::cta.b64 p, [%1], %2;\n\t"
        "selp.b32 %0, 1, 0, p;\n\t}"
        : "=r"(done) : "r"(addr), "r"(parity) : "memory");
    if (!done) {
        asm volatile(
            "{\n\t.reg .pred P1;\n\t"
            "WL_%=:\n\t"
            "mbarrier.try_wait.parity.acquire.cta.shared::cta.b64 P1, [%0], %1, 0x989680;\n\t"
            "@P1 bra.uni WD_%=;\n\t"
            "bra.uni WL_%=;\n\t"
            "WD_%=:\n\t}"
            :: "r"(addr), "r"(parity) : "memory");
    }
}
#define CLUSTER_SYNC() do { \
    asm volatile("barrier.cluster.arrive.aligned;" ::: "memory"); \
    asm volatile("barrier.cluster.wait.aligned;"   ::: "memory"); \
} while (0)

// ---------------------------------------------------------------------------
// Merged precompute kernel (one launch, full chip):
//   blocks [0,512):    HU[b,s,e] = sum_d H[b,s,d] * Ua[d,e]   (8 rows/block)
//   blocks [512,1024): XG[row, g*128+c] = b_g[c] + sum_k x[row,k]*W_g[k,c]
// float4 k-tiling: per 4k -> 4 LDG (W col) + 8 LDS.128 + 32 FMA.
// ---------------------------------------------------------------------------
__global__ __launch_bounds__(128) void pre_kernel(
    const float* __restrict__ H, const float* __restrict__ Ua,
    const float* __restrict__ x,
    const float* __restrict__ Wi, const float* __restrict__ Wf,
    const float* __restrict__ Wc, const float* __restrict__ Wo,
    const float* __restrict__ bi, const float* __restrict__ bf,
    const float* __restrict__ bc, const float* __restrict__ bo) {
    __shared__ __align__(16) float sA[8 * DD];
    const int tid = threadIdx.x;
    const int blk = blockIdx.x;

    const float* Asrc;
    const float* W;
    float bias = 0.f;
    float* dst;
    int dstride;
    if (blk < 512) {
        Asrc = H + (size_t)blk * 8 * DD;
        W = Ua;
        dst = g_HU + (size_t)blk * 8 * DD;
        dstride = DD;
    } else {
        const int idx = blk - 512;
        const int g = idx >> 7, rb = idx & 127;
        Asrc = x + (size_t)rb * 8 * DD;
        W = (g == 0) ? Wi : (g == 1) ? Wf : (g == 2) ? Wc : Wo;
        const float* bb = (g == 0) ? bi : (g == 1) ? bf : (g == 2) ? bc : bo;
        bias = __ldg(bb + tid);
        dst = g_XG + (size_t)rb * 8 * 512 + g * DD;
        dstride = 512;
    }
    #pragma unroll
    for (int i = 0; i < 8; i++) sA[i * DD + tid] = __ldg(Asrc + i * DD + tid);
    __syncthreads();

    float acc[8];
    #pragma unroll
    for (int r = 0; r < 8; r++) acc[r] = bias;
    #pragma unroll 4
    for (int k0 = 0; k0 < DD; k0 += 4) {
        const float w0 = __ldg(W + (k0 + 0) * DD + tid);
        const float w1 = __ldg(W + (k0 + 1) * DD + tid);
        const float w2 = __ldg(W + (k0 + 2) * DD + tid);
        const float w3 = __ldg(W + (k0 + 3) * DD + tid);
        #pragma unroll
        for (int r = 0; r < 8; r++) {
            const float4 a = *reinterpret_cast<const float4*>(&sA[r * DD + k0]);
            acc[r] += a.x * w0 + a.y * w1 + a.z * w2 + a.w * w3;
        }
    }
    #pragma unroll
    for (int r = 0; r < 8; r++) dst[r * dstride + tid] = acc[r];
}

// ---------------------------------------------------------------------------
// Recurrent kernel: 4 clusters x 8 CTAs; each cluster runs TWO batches,
// software-pipelined so each batch's DSMEM exchanges hide behind the other
// batch's compute. Rank r: attention rows [64r,64r+64); gate (r>>1) columns
// [(r&1)*64, +64). Wa/U/C slices register-cached. h@U hoisted before the
// ctx exchange.
// ---------------------------------------------------------------------------
// dynamic smem layout (floats):
#define O_HU0    0
#define O_HU1    8192
#define O_H0     16384
#define O_H1     24576
#define O_SH0    32768
#define O_SH1    32896
#define O_CELL0  33024
#define O_CELL1  33152
#define O_SQ0    33280
#define O_SQ1    33408
#define O_CTX0   33536
#define O_CTX1   33664
#define O_PART   33792
#define O_ZRED   35840
#define O_CBUF0  35856
#define O_CBUF1  36912
#define O_GBUF0  37968
#define O_GBUF1  38480
#define O_MBAR   38992
#define SM_FLOATS 39000

__device__ __forceinline__ void front_half(
    const float* __restrict__ sh, float* __restrict__ sq,
    const float* __restrict__ sHU, const float* __restrict__ sHs,
    float* __restrict__ part, float* __restrict__ zred,
    const float* waReg, const float* Ureg, float& hu,
    const float4 vreg, const int lane, const int wp,
    const int qp, const int gp) {
    // P1: q = h @ Wa (Wa in regs) + hU gate partial (h@U, hoisted)
    float accq = 0.f;
    float huv = 0.f;
    #pragma unroll
    for (int kk = 0; kk < 32; kk++) accq += sh[qp + 4 * kk] * waReg[kk];
    #pragma unroll
    for (int kk = 0; kk < 16; kk++) huv += sh[gp + 8 * kk] * Ureg[kk];
    hu = huv;
    accq += __shfl_xor_sync(0xffffffffu, accq, 8);
    accq += __shfl_xor_sync(0xffffffffu, accq, 16);
    if (lane < 8) sq[(wp << 3) + lane] = accq;
    __syncthreads();

    // P2: scores -> exp -> ctx partial (no-max softmax: |score|<=sum|v|~5)
    const float4 q4 = *reinterpret_cast<const float4*>(&sq[lane * 4]);
    float4 ctx4 = make_float4(0.f, 0.f, 0.f, 0.f);
    float zp = 0.f;
    #pragma unroll
    for (int i = 0; i < 4; i++) {
        const int s = wp + (i << 4);
        const float4 hu4 = *reinterpret_cast<const float4*>(&sHU[s * DD + lane * 4]);
        float sc = tanh_ap(hu4.x + q4.x) * vreg.x
                 + tanh_ap(hu4.y + q4.y) * vreg.y
                 + tanh_ap(hu4.z + q4.z) * vreg.z
                 + tanh_ap(hu4.w + q4.w) * vreg.w;
        #pragma unroll
        for (int o = 16; o > 0; o >>= 1) sc += __shfl_xor_sync(0xffffffffu, sc, o);
        const float e = __expf(sc);
        zp += e;
        const float4 h4 = *reinterpret_cast<const float4*>(&sHs[s * DD + lane * 4]);
        ctx4.x += e * h4.x; ctx4.y += e * h4.y;
        ctx4.z += e * h4.z; ctx4.w += e * h4.w;
    }
    *reinterpret_cast<float4*>(&part[wp * DD + lane * 4]) = ctx4;
    if (lane == 0) zred[wp] = zp;
    __syncthreads();
}

__device__ __forceinline__ void send_ctx(
    const float* __restrict__ part, const float* __restrict__ zred,
    const uint32_t ctx_addr, const uint32_t z_addr, const uint32_t mbar,
    const int tid) {
    if (tid < DD) {
        float c = 0.f;
        #pragma unroll
        for (int w = 0; w < NWARP; w++) c += part[w * DD + tid];
        #pragma unroll
        for (int q = 0; q < CLUSTER; q++)
            st_async_remote(ctx_addr, mbar, (uint32_t)q, c);
    } else if (tid == DD) {
        float z = 0.f;
        #pragma unroll
        for (int w = 0; w < NWARP; w++) z += zred[w];
        #pragma unroll
        for (int q = 0; q < CLUSTER; q++)
            st_async_remote(z_addr, mbar, (uint32_t)q, z);
    }
}

__device__ __forceinline__ void back_half(
    float* __restrict__ sctx, const float* __restrict__ ctxbuf,
    const float hu, const float* Creg, const float xg,
    const uint32_t g_addr, const uint32_t gate_mbar,
    const uint32_t ctx_mbar, const uint32_t parity,
    const int tid, const int gp, const int gate) {
    mbar_wait(ctx_mbar, parity);
    if (tid < DD) {
        float Z = 0.f, c = 0.f;
        #pragma unroll
        for (int q = 0; q < CLUSTER; q++) {
            Z += ctxbuf[q * 132 + 128];
            c += ctxbuf[q * 132 + tid];
        }
        sctx[tid] = c / Z;
    }
    __syncthreads();
    float acc = hu;
    #pragma unroll
    for (int kk = 0; kk < 16; kk++) acc += sctx[gp + 8 * kk] * Creg[kk];
    acc += __shfl_xor_sync(0xffffffffu, acc, 1);
    acc += __shfl_xor_sync(0xffffffffu, acc, 2);
    acc += __shfl_xor_sync(0xffffffffu, acc, 4);
    const float pre = acc + xg;
    const float act = (gate == 2) ? tanhf(pre) : 1.f / (1.f + __expf(-pre));
    st_async_remote(g_addr, gate_mbar, (uint32_t)gp, act);
}

__global__ __launch_bounds__(NTHR, 1) __cluster_dims__(CLUSTER, 1, 1)
void rec_kernel(const float* __restrict__ H, const float* __restrict__ init,
                const float* __restrict__ Wa, const float* __restrict__ v,
                const float* __restrict__ Ui, const float* __restrict__ Ci,
                const float* __restrict__ Uf, const float* __restrict__ Cf,
                const float* __restrict__ Uc, const float* __restrict__ Cc,
                const float* __restrict__ Uo, const float* __restrict__ Co,
                float* __restrict__ out) {
    extern __shared__ __align__(16) float dsm[];
    const int tid  = threadIdx.x;
    const int lane = tid & 31;
    const int wp   = tid >> 5;
    const int cl   = blockIdx.x >> 3;   // cluster id -> batches 2cl, 2cl+1
    const int rk   = blockIdx.x & 7;    // cluster rank
    const int b0   = 2 * cl;
    const int b1   = 2 * cl + 1;

    float* sHU0 = dsm + O_HU0;  float* sHU1 = dsm + O_HU1;
    float* sH0  = dsm + O_H0;   float* sH1  = dsm + O_H1;
    float* sh0  = dsm + O_SH0;  float* sh1  = dsm + O_SH1;
    float* sc0  = dsm + O_CELL0; float* sc1 = dsm + O_CELL1;
    float* sq0  = dsm + O_SQ0;  float* sq1  = dsm + O_SQ1;
    float* sx0  = dsm + O_CTX0; float* sx1  = dsm + O_CTX1;
    float* part = dsm + O_PART; float* zred = dsm + O_ZRED;
    float* cbuf0 = dsm + O_CBUF0; float* cbuf1 = dsm + O_CBUF1;
    float* gbuf0 = dsm + O_GBUF0; float* gbuf1 = dsm + O_GBUF1;
    float* mbars = dsm + O_MBAR;

    const uint32_t ctx_mbar0  = smem_u32(&mbars[0]);
    const uint32_t ctx_mbar1  = smem_u32(&mbars[2]);
    const uint32_t gate_mbar0 = smem_u32(&mbars[4]);
    const uint32_t gate_mbar1 = smem_u32(&mbars[6]);

    // ---------------- prologue ----------------
    if (tid == 0) {
        mbar_init(ctx_mbar0, 1);
        mbar_init(ctx_mbar1, 1);
        mbar_init(gate_mbar0, 1);
        mbar_init(gate_mbar1, 1);
        asm volatile("fence.mbarrier_init.release.cluster;" ::: "memory");
    }
    {
        const float4* HU0 = (const float4*)(g_HU + (size_t)(b0 * SS + rk * SSLICE) * DD);
        const float4* HU1 = (const float4*)(g_HU + (size_t)(b1 * SS + rk * SSLICE) * DD);
        const float4* Hs0 = (const float4*)(H    + (size_t)(b0 * SS + rk * SSLICE) * DD);
        const float4* Hs1 = (const float4*)(H    + (size_t)(b1 * SS + rk * SSLICE) * DD);
        float4* dHU0 = (float4*)sHU0; float4* dHU1 = (float4*)sHU1;
        float4* dH0  = (float4*)sH0;  float4* dH1  = (float4*)sH1;
        #pragma unroll
        for (int i = 0; i < 4; i++) {
            const int ix = tid + i * NTHR;
            dHU0[ix] = HU0[ix]; dHU1[ix] = HU1[ix];
            dH0[ix]  = Hs0[ix]; dH1[ix]  = Hs1[ix];
        }
        if (tid < DD) {
            sh0[tid] = init[b0 * DD + tid];
            sh1[tid] = init[b1 * DD + tid];
            sc0[tid] = init[BB * DD + b0 * DD + tid];
            sc1[tid] = init[BB * DD + b1 * DD + tid];
        }
    }

    const float4 vreg = ldg4(v + 4 * lane);

    // P1 layout: warp wp -> q cols [8wp,8wp+8); col = 8wp+(lane&7), part qp=lane>>3
    const int qcol = (wp << 3) + (lane & 7);
    const int qp   = lane >> 3;
    float waReg[32];
    #pragma unroll
    for (int kk = 0; kk < 32; kk++)
        waReg[kk] = __ldg(Wa + (qp + 4 * kk) * DD + qcol);

    // gate layout: gate = rk>>1, cols gc0+[0,64); col = gc0+(tid>>3), part gp=tid&7
    const int gate = rk >> 1;
    const int gc0  = (rk & 1) * 64;
    const int gcol = gc0 + (tid >> 3);
    const int gp   = tid & 7;
    const float* Ug = (gate == 0) ? Ui : (gate == 1) ? Uf : (gate == 2) ? Uc : Uo;
    const float* Cg = (gate == 0) ? Ci : (gate == 1) ? Cf : (gate == 2) ? Cc : Co;
    float Ureg[16], Creg[16];
    #pragma unroll
    for (int kk = 0; kk < 16; kk++) {
        const int k = gp + 8 * kk;
        Ureg[kk] = __ldg(Ug + k * DD + gcol);
        Creg[kk] = __ldg(Cg + k * DD + gcol);
    }

    const float* XG0 = g_XG + (size_t)b0 * TT * 512;
    const float* XG1 = g_XG + (size_t)b1 * TT * 512;

    // local mailbox slot addresses (same offsets cluster-wide; sender-indexed)
    const uint32_t ctx_addr0 = (tid < DD) ? smem_u32(&cbuf0[rk * 132 + tid]) : 0u;
    const uint32_t ctx_addr1 = (tid < DD) ? smem_u32(&cbuf1[rk * 132 + tid]) : 0u;
    const uint32_t z_addr0   = smem_u32(&cbuf0[rk * 132 + 128]);
    const uint32_t z_addr1   = smem_u32(&cbuf1[rk * 132 + 128]);
    const uint32_t g_addr0   = smem_u32(&gbuf0[gate * DD + gcol]);
    const uint32_t g_addr1   = smem_u32(&gbuf1[gate * DD + gcol]);

    __syncthreads();
    CLUSTER_SYNC();   // mbarriers + smem ready on every rank

    for (int t = 0; t < TT; t++) {
        const uint32_t parity = (uint32_t)(t & 1);
        if (tid == 0) {
            mbar_expect_tx(ctx_mbar0,  CLUSTER * 129 * 4);
            mbar_expect_tx(ctx_mbar1,  CLUSTER * 129 * 4);
            mbar_expect_tx(gate_mbar0, 512 * 4);
            mbar_expect_tx(gate_mbar1, 512 * 4);
        }
        const float xg0 = __ldg(XG0 + t * 512 + gate * DD + gcol);
        const float xg1 = __ldg(XG1 + t * 512 + gate * DD + gcol);

        float hu0, hu1;
        // ---- batch 0 front ----
        front_half(sh0, sq0, sHU0, sH0, part, zred, waReg, Ureg, hu0,
                   vreg, lane, wp, qp, gp);
        send_ctx(part, zred, ctx_addr0, z_addr0, ctx_mbar0, tid);
        // ---- batch 1 front (hides ctx0 exchange) ----
        front_half(sh1, sq1, sHU1, sH1, part, zred, waReg, Ureg, hu1,
                   vreg, lane, wp, qp, gp);
        send_ctx(part, zred, ctx_addr1, z_addr1, ctx_mbar1, tid);
        // ---- batch 0 back (hides ctx1 exchange) ----
        back_half(sx0, cbuf0, hu0, Creg, xg0, g_addr0, gate_mbar0,
                  ctx_mbar0, parity, tid, gp, gate);
        // ---- batch 1 back (hides gate0 exchange) ----
        back_half(sx1, cbuf1, hu1, Creg, xg1, g_addr1, gate_mbar1,
                  ctx_mbar1, parity, tid, gp, gate);

        // ---- LSTM updates (parallel thread ranges) ----
        mbar_wait(gate_mbar0, parity);
        mbar_wait(gate_mbar1, parity);
        if (tid < DD) {
            const float ig = gbuf0[tid];
            const float fg = gbuf0[DD + tid];
            const float gw = gbuf0[2 * DD + tid];
            const float og = gbuf0[3 * DD + tid];
            const float cn = fg * sc0[tid] + ig * gw;
            const float hn = og * tanhf(cn);
            sc0[tid] = cn;
            sh0[tid] = hn;
            if (rk == 0) out[(size_t)(b0 * TT + t) * DD + tid] = hn;
        } else if (tid < 2 * DD) {
            const int d = tid - DD;
            const float ig = gbuf1[d];
            const float fg = gbuf1[DD + d];
            const float gw = gbuf1[2 * DD + d];
            const float og = gbuf1[3 * DD + d];
            const float cn = fg * sc1[d] + ig * gw;
            const float hn = og * tanhf(cn);
            sc1[d] = cn;
            sh1[d] = hn;
            if (rk == 0) out[(size_t)(b1 * TT + t) * DD + d] = hn;
        }
        __syncthreads();
    }
}

// ---------------------------------------------------------------------------
extern "C" void kernel_launch(void* const* d_in, const int* in_sizes, int n_in,
                              void* d_out, int out_size) {
    const float* x    = (const float*)d_in[0];
    const float* H    = (const float*)d_in[1];
    const float* init = (const float*)d_in[2];
    const float* Wa   = (const float*)d_in[3];
    const float* Ua   = (const float*)d_in[4];
    const float* v    = (const float*)d_in[5];
    const float* Wi   = (const float*)d_in[6];
    const float* Ui   = (const float*)d_in[7];
    const float* Ci   = (const float*)d_in[8];
    const float* bi   = (const float*)d_in[9];
    const float* Wf   = (const float*)d_in[10];
    const float* Uf   = (const float*)d_in[11];
    const float* Cf   = (const float*)d_in[12];
    const float* bf   = (const float*)d_in[13];
    const float* Wc   = (const float*)d_in[14];
    const float* Uc   = (const float*)d_in[15];
    const float* Cc   = (const float*)d_in[16];
    const float* bc   = (const float*)d_in[17];
    const float* Wo   = (const float*)d_in[18];
    const float* Uo   = (const float*)d_in[19];
    const float* Co   = (const float*)d_in[20];
    const float* bo   = (const float*)d_in[21];
    float* out = (float*)d_out;

    static bool attr_set = false;
    if (!attr_set) {
        cudaFuncSetAttribute(rec_kernel,
                             cudaFuncAttributeMaxDynamicSharedMemorySize,
                             SM_FLOATS * sizeof(float));
        attr_set = true;
    }

    pre_kernel<<<1024, 128>>>(H, Ua, x, Wi, Wf, Wc, Wo, bi, bf, bc, bo);
    rec_kernel<<<BB / 2 * CLUSTER, NTHR, SM_FLOATS * sizeof(float)>>>(
        H, init, Wa, v, Ui, Ci, Uf, Cf, Uc, Cc, Uo, Co, out);
}

// round 7
// speedup vs baseline: 1.5825x; 1.5825x over previous
#include <cuda_runtime.h>
#include <cuda_bf16.h>
#include <cstdint>

// Problem constants
#define BB 8
#define TT 128
#define SS 512
#define DD 128
#define CLUSTER 8
#define SSLICE (SS / CLUSTER)   // 64 encoder rows per rank
#define NTHR 512
#define NWARP 16

// Scratch (allocation-free rule: __device__ globals)
__device__ float g_HU[BB * SS * DD];   // H @ Ua, [B,S,D]
__device__ float g_XG[BB * TT * 512];  // x@W + bias for 4 gates (i,f,c,o), [B,T,512]

__device__ __forceinline__ float tanh_ap(float x) {
    float y;
    asm("tanh.approx.f32 %0, %1;" : "=f"(y) : "f"(x));
    return y;
}
__device__ __forceinline__ float4 ldg4(const float* p) {
    return __ldg(reinterpret_cast<const float4*>(p));
}
__device__ __forceinline__ uint32_t smem_u32(const void* p) {
    uint32_t a;
    asm("{ .reg .u64 t; cvta.to.shared.u64 t, %1; cvt.u32.u64 %0, t; }" : "=r"(a) : "l"(p));
    return a;
}
// st.async a float to the SAME smem offset on cluster CTA `rank`, completing
// tx bytes on that rank's mbarrier.
__device__ __forceinline__ void st_async_remote(uint32_t laddr, uint32_t lmbar,
                                                uint32_t rank, float v) {
    uint32_t ra, rb;
    asm volatile("mapa.shared::cluster.u32 %0, %1, %2;" : "=r"(ra) : "r"(laddr), "r"(rank));
    asm volatile("mapa.shared::cluster.u32 %0, %1, %2;" : "=r"(rb) : "r"(lmbar), "r"(rank));
    asm volatile("st.async.shared::cluster.mbarrier::complete_tx::bytes.b32 [%0], %1, [%2];"
                 :: "r"(ra), "r"(__float_as_uint(v)), "r"(rb) : "memory");
}
// 16-byte packed variant: 4 floats per DSMEM message.
__device__ __forceinline__ void st_async_remote_v4(uint32_t laddr, uint32_t lmbar,
                                                   uint32_t rank, float a, float b,
                                                   float c, float d) {
    uint32_t ra, rb;
    asm volatile("mapa.shared::cluster.u32 %0, %1, %2;" : "=r"(ra) : "r"(laddr), "r"(rank));
    asm volatile("mapa.shared::cluster.u32 %0, %1, %2;" : "=r"(rb) : "r"(lmbar), "r"(rank));
    asm volatile("st.async.shared::cluster.mbarrier::complete_tx::bytes.v4.b32 "
                 "[%0], {%1, %2, %3, %4}, [%5];"
                 :: "r"(ra), "r"(__float_as_uint(a)), "r"(__float_as_uint(b)),
                    "r"(__float_as_uint(c)), "r"(__float_as_uint(d)), "r"(rb) : "memory");
}
__device__ __forceinline__ void mbar_init(uint32_t addr, uint32_t count) {
    asm volatile("mbarrier.init.shared.b64 [%0], %1;" :: "r"(addr), "r"(count) : "memory");
}
__device__ __forceinline__ void mbar_expect_tx(uint32_t addr, uint32_t bytes) {
    asm volatile("mbarrier.arrive.expect_tx.shared.b64 _, [%0], %1;"
                 :: "r"(addr), "r"(bytes) : "memory");
}
__device__ __forceinline__ void mbar_wait(uint32_t addr, uint32_t parity) {
    uint32_t done;
    asm volatile(
        "{\n\t.reg .pred p;\n\t"
        "mbarrier.try_wait.parity.acquire.cta.shared::cta.b64 p, [%1], %2;\n\t"
        "selp.b32 %0, 1, 0, p;\n\t}"
        : "=r"(done) : "r"(addr), "r"(parity) : "memory");
    if (!done) {
        asm volatile(
            "{\n\t.reg .pred P1;\n\t"
            "WL_%=:\n\t"
            "mbarrier.try_wait.parity.acquire.cta.shared::cta.b64 P1, [%0], %1, 0x989680;\n\t"
            "@P1 bra.uni WD_%=;\n\t"
            "bra.uni WL_%=;\n\t"
            "WD_%=:\n\t}"
            :: "r"(addr), "r"(parity) : "memory");
    }
}
#define CLUSTER_SYNC() do { \
    asm volatile("barrier.cluster.arrive.aligned;" ::: "memory"); \
    asm volatile("barrier.cluster.wait.aligned;"   ::: "memory"); \
} while (0)

// ---------------------------------------------------------------------------
// Merged precompute kernel (one launch, full chip):
//   blocks [0,512):    HU[b,s,e] = sum_d H[b,s,d] * Ua[d,e]   (8 rows/block)
//   blocks [512,1024): XG[row, g*128+c] = b_g[c] + sum_k x[row,k]*W_g[k,c]
// ---------------------------------------------------------------------------
__global__ __launch_bounds__(128) void pre_kernel(
    const float* __restrict__ H, const float* __restrict__ Ua,
    const float* __restrict__ x,
    const float* __restrict__ Wi, const float* __restrict__ Wf,
    const float* __restrict__ Wc, const float* __restrict__ Wo,
    const float* __restrict__ bi, const float* __restrict__ bf,
    const float* __restrict__ bc, const float* __restrict__ bo) {
    __shared__ __align__(16) float sA[8 * DD];
    const int tid = threadIdx.x;
    const int blk = blockIdx.x;

    const float* Asrc;
    const float* W;
    float bias = 0.f;
    float* dst;
    int dstride;
    if (blk < 512) {
        Asrc = H + (size_t)blk * 8 * DD;
        W = Ua;
        dst = g_HU + (size_t)blk * 8 * DD;
        dstride = DD;
    } else {
        const int idx = blk - 512;
        const int g = idx >> 7, rb = idx & 127;
        Asrc = x + (size_t)rb * 8 * DD;
        W = (g == 0) ? Wi : (g == 1) ? Wf : (g == 2) ? Wc : Wo;
        const float* bb = (g == 0) ? bi : (g == 1) ? bf : (g == 2) ? bc : bo;
        bias = __ldg(bb + tid);
        dst = g_XG + (size_t)rb * 8 * 512 + g * DD;
        dstride = 512;
    }
    #pragma unroll
    for (int i = 0; i < 8; i++) sA[i * DD + tid] = __ldg(Asrc + i * DD + tid);
    __syncthreads();

    float acc[8];
    #pragma unroll
    for (int r = 0; r < 8; r++) acc[r] = bias;
    #pragma unroll 4
    for (int k0 = 0; k0 < DD; k0 += 4) {
        const float w0 = __ldg(W + (k0 + 0) * DD + tid);
        const float w1 = __ldg(W + (k0 + 1) * DD + tid);
        const float w2 = __ldg(W + (k0 + 2) * DD + tid);
        const float w3 = __ldg(W + (k0 + 3) * DD + tid);
        #pragma unroll
        for (int r = 0; r < 8; r++) {
            const float4 a = *reinterpret_cast<const float4*>(&sA[r * DD + k0]);
            acc[r] += a.x * w0 + a.y * w1 + a.z * w2 + a.w * w3;
        }
    }
    #pragma unroll
    for (int r = 0; r < 8; r++) dst[r * dstride + tid] = acc[r];
}

// ---------------------------------------------------------------------------
// Recurrent kernel: 8 clusters x 8 CTAs, ONE batch per cluster. Rank r:
//   - attention over encoder rows [64r, 64r+64)  (HU, H slices in smem)
//   - gate (r>>1), columns [(r&1)*64, +64)       (U, C in registers)
// Exchanges via packed st.async.v4 + mbarrier; h@U hoisted before ctx wait;
// softmax normalization deferred to a single invZ multiply in the gate GEMV.
// ---------------------------------------------------------------------------
// dynamic smem layout (floats):
//   sHU   [0     ,  8192)   HU slice (64 x 128)
//   sH    [8192  , 16384)   H slice
//   sh    [16384 , 16512)
//   scell [16512 , 16640)
//   sq    [16640 , 16768)
//   sctx  [16768 , 16896)   UNNORMALIZED ctx sum
//   part  [16896 , 18944)   16 x 128 ctx warp partials
//   zred  [18944 , 18960)
//   ctxbuf[18960 , 20016)   8 x 132 mailbox (ctx[128] + z at [128])
//   gbuf  [20016 , 20528)   4 x 128 gate mailbox
//   mbars [20528 , 20532)   2 x u64 (ctx, gate)
//   invZ  [20532 , 20533)
#define SM_FLOATS 20536

__global__ __launch_bounds__(NTHR, 1) __cluster_dims__(CLUSTER, 1, 1)
void rec_kernel(const float* __restrict__ H, const float* __restrict__ init,
                const float* __restrict__ Wa, const float* __restrict__ v,
                const float* __restrict__ Ui, const float* __restrict__ Ci,
                const float* __restrict__ Uf, const float* __restrict__ Cf,
                const float* __restrict__ Uc, const float* __restrict__ Cc,
                const float* __restrict__ Uo, const float* __restrict__ Co,
                float* __restrict__ out) {
    extern __shared__ __align__(16) float dsm[];
    float* sHU    = dsm;
    float* sHs    = dsm + 8192;
    float* sh     = dsm + 16384;
    float* scell  = dsm + 16512;
    float* sq     = dsm + 16640;
    float* sctx   = dsm + 16768;
    float* part   = dsm + 16896;
    float* zred   = dsm + 18944;
    float* ctxbuf = dsm + 18960;
    float* gbuf   = dsm + 20016;
    float* mbars  = dsm + 20528;
    float* s_invZ = dsm + 20532;

    const int tid  = threadIdx.x;
    const int lane = tid & 31;
    const int wp   = tid >> 5;
    const int b    = blockIdx.x >> 3;   // batch
    const int rk   = blockIdx.x & 7;    // cluster rank

    const uint32_t ctx_mbar  = smem_u32(&mbars[0]);
    const uint32_t gate_mbar = smem_u32(&mbars[2]);

    // ---------------- prologue ----------------
    if (tid == 0) {
        mbar_init(ctx_mbar, 1);
        mbar_init(gate_mbar, 1);
        asm volatile("fence.mbarrier_init.release.cluster;" ::: "memory");
    }
    {
        const float4* HUsrc = (const float4*)(g_HU + (size_t)(b * SS + rk * SSLICE) * DD);
        const float4* Hsrc  = (const float4*)(H    + (size_t)(b * SS + rk * SSLICE) * DD);
        float4* dHU = (float4*)sHU;
        float4* dH  = (float4*)sHs;
        #pragma unroll
        for (int i = 0; i < 4; i++) {
            dHU[tid + i * NTHR] = HUsrc[tid + i * NTHR];
            dH[tid + i * NTHR]  = Hsrc[tid + i * NTHR];
        }
        if (tid < DD) {
            sh[tid]    = init[b * DD + tid];
            scell[tid] = init[BB * DD + b * DD + tid];
        }
    }

    // v cached per-lane (float4 of 4 consecutive d)
    const float4 vreg = ldg4(v + 4 * lane);

    // P1 layout: warp wp -> q cols [8wp,8wp+8); col = 8wp+(lane&7), part qp=lane>>3
    const int qcol = (wp << 3) + (lane & 7);
    const int qp   = lane >> 3;
    float waReg[32];
    #pragma unroll
    for (int kk = 0; kk < 32; kk++)
        waReg[kk] = __ldg(Wa + (qp + 4 * kk) * DD + qcol);

    // gate layout: gate = rk>>1, cols gc0+[0,64); col = gc0+(tid>>3), part gp=tid&7
    const int gate = rk >> 1;
    const int gc0  = (rk & 1) * 64;
    const int gcol = gc0 + (tid >> 3);
    const int gp   = tid & 7;
    const float* Ug = (gate == 0) ? Ui : (gate == 1) ? Uf : (gate == 2) ? Uc : Uo;
    const float* Cg = (gate == 0) ? Ci : (gate == 1) ? Cf : (gate == 2) ? Cc : Co;
    float Ureg[16], Creg[16];
    #pragma unroll
    for (int kk = 0; kk < 16; kk++) {
        const int k = gp + 8 * kk;
        Ureg[kk] = __ldg(Ug + k * DD + gcol);
        Creg[kk] = __ldg(Cg + k * DD + gcol);
    }

    const float* XGb = g_XG + (size_t)b * TT * 512;

    // Mailbox slot addresses (same smem offsets cluster-wide; sender-indexed).
    // ctx: thread tid (tid<128, tid%4==0) sends float4 for d=[tid,tid+4).
    const uint32_t ctx_addr = (tid < DD) ? smem_u32(&ctxbuf[rk * 132 + tid]) : 0u;
    const uint32_t zsl_addr = smem_u32(&ctxbuf[rk * 132 + 128]);
    // gate: lane<8 of warp wp sends float4 for cols gc0+4wp+[0,4) to rank=lane.
    const uint32_t g_addr   = smem_u32(&gbuf[gate * DD + gc0 + 4 * wp]);

    __syncthreads();
    CLUSTER_SYNC();   // mbarriers + smem ready on every rank

    for (int t = 0; t < TT; t++) {
        const uint32_t parity = (uint32_t)(t & 1);
        if (tid == 0) {
            mbar_expect_tx(ctx_mbar,  CLUSTER * 129 * 4);
            mbar_expect_tx(gate_mbar, 512 * 4);
        }
        // prefetch this step's x-gate contribution
        const float xg = __ldg(XGb + t * 512 + gate * DD + gcol);

        // ---------- P1: q = h @ Wa (regs) + hoisted h@U gate partial ----------
        float hu;
        {
            float accq = 0.f, huv = 0.f;
            #pragma unroll
            for (int kk = 0; kk < 32; kk++) accq += sh[qp + 4 * kk] * waReg[kk];
            #pragma unroll
            for (int kk = 0; kk < 16; kk++) huv += sh[gp + 8 * kk] * Ureg[kk];
            hu = huv;
            accq += __shfl_xor_sync(0xffffffffu, accq, 8);
            accq += __shfl_xor_sync(0xffffffffu, accq, 16);
            if (lane < 8) sq[(wp << 3) + lane] = accq;
        }
        __syncthreads();  // A

        // ---------- P2: scores -> exp -> ctx partial (no-max softmax:
        // |score| <= sum|v| ~ 5, exp is safe) ----------
        {
            const float4 q4 = *reinterpret_cast<const float4*>(&sq[lane * 4]);
            float4 ctx4 = make_float4(0.f, 0.f, 0.f, 0.f);
            float zp = 0.f;
            #pragma unroll
            for (int i = 0; i < 4; i++) {
                const int s = wp + (i << 4);
                const float4 hu4 = *reinterpret_cast<const float4*>(&sHU[s * DD + lane * 4]);
                float sc = tanh_ap(hu4.x + q4.x) * vreg.x
                         + tanh_ap(hu4.y + q4.y) * vreg.y
                         + tanh_ap(hu4.z + q4.z) * vreg.z
                         + tanh_ap(hu4.w + q4.w) * vreg.w;
                #pragma unroll
                for (int o = 16; o > 0; o >>= 1) sc += __shfl_xor_sync(0xffffffffu, sc, o);
                const float e = __expf(sc);
                zp += e;
                const float4 h4 = *reinterpret_cast<const float4*>(&sHs[s * DD + lane * 4]);
                ctx4.x += e * h4.x; ctx4.y += e * h4.y;
                ctx4.z += e * h4.z; ctx4.w += e * h4.w;
            }
            *reinterpret_cast<float4*>(&part[wp * DD + lane * 4]) = ctx4;
            if (lane == 0) zred[wp] = zp;
        }
        __syncthreads();  // B

        // ---------- exchange 1: packed (ctx_r, z_r) -> all ranks ----------
        if (tid < DD) {
            float c = 0.f;
            #pragma unroll
            for (int w = 0; w < NWARP; w++) c += part[w * DD + tid];
            const float c1 = __shfl_down_sync(0xffffffffu, c, 1);
            const float c2 = __shfl_down_sync(0xffffffffu, c, 2);
            const float c3 = __shfl_down_sync(0xffffffffu, c, 3);
            if ((lane & 3) == 0) {
                #pragma unroll
                for (int q = 0; q < CLUSTER; q++)
                    st_async_remote_v4(ctx_addr, ctx_mbar, (uint32_t)q, c, c1, c2, c3);
            }
        } else if (tid == DD) {
            float z = 0.f;
            #pragma unroll
            for (int w = 0; w < NWARP; w++) z += zred[w];
            #pragma unroll
            for (int q = 0; q < CLUSTER; q++)
                st_async_remote(zsl_addr, ctx_mbar, (uint32_t)q, z);
        }
        mbar_wait(ctx_mbar, parity);

        // ---------- combine: sctx = sum_r ctx_r (unnormalized); invZ once ----------
        if (tid < DD) {
            float c = 0.f;
            #pragma unroll
            for (int q = 0; q < CLUSTER; q++) c += ctxbuf[q * 132 + tid];
            sctx[tid] = c;
        } else if (tid == DD) {
            float Z = 0.f;
            #pragma unroll
            for (int q = 0; q < CLUSTER; q++) Z += ctxbuf[q * 132 + 128];
            s_invZ[0] = 1.f / Z;
        }
        __syncthreads();  // C

        // ---------- P4: gate slice; normalization folded into invZ multiply ----------
        {
            const float invZ = s_invZ[0];
            float acc = 0.f;
            #pragma unroll
            for (int kk = 0; kk < 16; kk++) acc += sctx[gp + 8 * kk] * Creg[kk];
            float p = hu + acc * invZ;
            p += __shfl_xor_sync(0xffffffffu, p, 1);
            p += __shfl_xor_sync(0xffffffffu, p, 2);
            p += __shfl_xor_sync(0xffffffffu, p, 4);
            const float pre = p + xg;
            const float act = (gate == 2) ? tanhf(pre) : 1.f / (1.f + __expf(-pre));
            // pack 4 consecutive cols (one per 8-lane subgroup) and ship to rank=lane
            const float a1 = __shfl_xor_sync(0xffffffffu, act, 8);
            const float a2 = __shfl_xor_sync(0xffffffffu, act, 16);
            const float a3 = __shfl_xor_sync(0xffffffffu, act, 24);
            if (lane < 8)
                st_async_remote_v4(g_addr, gate_mbar, (uint32_t)lane, act, a1, a2, a3);
        }
        mbar_wait(gate_mbar, parity);

        // ---------- LSTM update (duplicated on every rank) ----------
        if (tid < DD) {
            const float ig = gbuf[tid];
            const float fg = gbuf[DD + tid];
            const float gw = gbuf[2 * DD + tid];
            const float og = gbuf[3 * DD + tid];
            const float cn = fg * scell[tid] + ig * gw;
            const float hn = og * tanhf(cn);
            scell[tid] = cn;
            sh[tid]    = hn;
            if (rk == 0) out[(size_t)(b * TT + t) * DD + tid] = hn;
        }
        __syncthreads();  // D
    }
}

// ---------------------------------------------------------------------------
extern "C" void kernel_launch(void* const* d_in, const int* in_sizes, int n_in,
                              void* d_out, int out_size) {
    const float* x    = (const float*)d_in[0];
    const float* H    = (const float*)d_in[1];
    const float* init = (const float*)d_in[2];
    const float* Wa   = (const float*)d_in[3];
    const float* Ua   = (const float*)d_in[4];
    const float* v    = (const float*)d_in[5];
    const float* Wi   = (const float*)d_in[6];
    const float* Ui   = (const float*)d_in[7];
    const float* Ci   = (const float*)d_in[8];
    const float* bi   = (const float*)d_in[9];
    const float* Wf   = (const float*)d_in[10];
    const float* Uf   = (const float*)d_in[11];
    const float* Cf   = (const float*)d_in[12];
    const float* bf   = (const float*)d_in[13];
    const float* Wc   = (const float*)d_in[14];
    const float* Uc   = (const float*)d_in[15];
    const float* Cc   = (const float*)d_in[16];
    const float* bc   = (const float*)d_in[17];
    const float* Wo   = (const float*)d_in[18];
    const float* Uo   = (const float*)d_in[19];
    const float* Co   = (const float*)d_in[20];
    const float* bo   = (const float*)d_in[21];
    float* out = (float*)d_out;

    static bool attr_set = false;
    if (!attr_set) {
        cudaFuncSetAttribute(rec_kernel,
                             cudaFuncAttributeMaxDynamicSharedMemorySize,
                             SM_FLOATS * sizeof(float));
        attr_set = true;
    }

    pre_kernel<<<1024, 128>>>(H, Ua, x, Wi, Wf, Wc, Wo, bi, bf, bc, bo);
    rec_kernel<<<BB * CLUSTER, NTHR, SM_FLOATS * sizeof(float)>>>(
        H, init, Wa, v, Ui, Ci, Uf, Cf, Uc, Cc, Uo, Co, out);
}